// round 6
// baseline (speedup 1.0000x reference)
#include <cuda_runtime.h>
#include <math.h>
#include <float.h>

#define XG 432
#define YG 496
#define CO 64
#define NPT 32
#define PMAX 64000
#define BMAX 4

// Scratch (no allocations allowed anywhere)
__device__ int   g_winner[BMAX * XG * YG];
__device__ float g_pooled[PMAX * CO];

// ---------------------------------------------------------------------------
// Kernel 1: reset winner map
// ---------------------------------------------------------------------------
__global__ void init_winner_k(int n) {
    int i = blockIdx.x * blockDim.x + threadIdx.x;
    if (i < n) g_winner[i] = -1;
}

// ---------------------------------------------------------------------------
// Kernel 2: last-pillar-index-wins per BEV cell (deterministic via atomicMax)
// coors is int32 (JAX default x64-disabled turns int64 into int32).
// ---------------------------------------------------------------------------
__global__ void winner_k(const int* __restrict__ coors, int P, int B) {
    int p = blockIdx.x * blockDim.x + threadIdx.x;
    if (p >= P) return;
    int b = coors[4 * p + 0];
    int x = coors[4 * p + 1];
    int y = coors[4 * p + 2];
    if ((unsigned)b >= (unsigned)B || (unsigned)x >= XG || (unsigned)y >= YG)
        return;  // defensive: never fault, wrong values show up as rel_err
    atomicMax(&g_winner[(b * XG + x) * YG + y], p);
}

// ---------------------------------------------------------------------------
// Kernel 3: per-pillar PFN. One block (256 threads) per pillar.
//   threads: o = tid & 63 (output channel), ng = tid >> 6 (point group of 8)
// ---------------------------------------------------------------------------
__global__ __launch_bounds__(256) void mlp_k(
    const float* __restrict__ pillars,
    const int*   __restrict__ coors,
    const int*   __restrict__ npoints,
    const float* __restrict__ W1, const float* __restrict__ g1,
    const float* __restrict__ b1, const float* __restrict__ m1,
    const float* __restrict__ v1,
    const float* __restrict__ W2, const float* __restrict__ g2,
    const float* __restrict__ b2, const float* __restrict__ m2,
    const float* __restrict__ v2)
{
    __shared__ float s_raw[NPT * 4];       // raw points (x,y,z,r)
    __shared__ float s_f[NPT * 6];         // 6-channel features
    __shared__ float s_w1[6 * 64];         // W1 transposed: [c][o]
    __shared__ float s_w2[64 * 65];        // W2 transposed + pad: [c][o] stride 65
    __shared__ float s_h1[NPT * 64];       // layer-1 activations [n][o]
    __shared__ float s_part[4 * 64];       // per-group partial max
    __shared__ float s_meta[8];            // cx, cy, cz, px, py

    const int p   = blockIdx.x;
    const int tid = threadIdx.x;
    const int o   = tid & 63;
    const int ng  = tid >> 6;

    // ---- load raw points (coalesced: 128 floats) ----
    if (tid < 128) s_raw[tid] = pillars[p * 128 + tid];

    // ---- stage W1 transposed ----
    if (tid >= 128 && tid < 256) {
        for (int i = tid - 128; i < 384; i += 128) {
            int oo = i / 6, cc = i % 6;
            s_w1[cc * 64 + oo] = W1[i];
        }
    }
    // ---- stage W2 transposed with pad-65 (conflict-free loads later) ----
    for (int i = tid; i < 4096; i += 256) {
        int oo = i >> 6, cc = i & 63;
        s_w2[cc * 65 + oo] = W2[i];
    }
    __syncthreads();

    const int npf = npoints[p];

    // ---- center = sum over ALL 32 points (incl. padding) / npf ----
    if (tid < 32) {
        float sx = s_raw[tid * 4 + 0];
        float sy = s_raw[tid * 4 + 1];
        float sz = s_raw[tid * 4 + 2];
        #pragma unroll
        for (int off = 16; off > 0; off >>= 1) {
            sx += __shfl_down_sync(0xffffffffu, sx, off);
            sy += __shfl_down_sync(0xffffffffu, sy, off);
            sz += __shfl_down_sync(0xffffffffu, sz, off);
        }
        if (tid == 0) {
            float inv = 1.0f / (float)npf;
            s_meta[0] = sx * inv;
            s_meta[1] = sy * inv;
            s_meta[2] = sz * inv;
            int xi = coors[4 * p + 1];
            int yi = coors[4 * p + 2];
            s_meta[3] = (float)xi * 0.16f + 0.08f;    // pillar geometric center x
            s_meta[4] = (float)yi * 0.16f - 39.6f;    // pillar geometric center y
        }
    }
    __syncthreads();

    // ---- build features: [z, x-cx, y-cy, z-cz, x-px, y-py], masked ----
    if (tid < 192) {
        int n = tid / 6, c = tid % 6;
        float x = s_raw[n * 4 + 0];
        float y = s_raw[n * 4 + 1];
        float z = s_raw[n * 4 + 2];
        float val;
        switch (c) {
            case 0: val = z;             break;
            case 1: val = x - s_meta[0]; break;
            case 2: val = y - s_meta[1]; break;
            case 3: val = z - s_meta[2]; break;
            case 4: val = x - s_meta[3]; break;
            default: val = y - s_meta[4]; break;
        }
        if (n >= npf) val = 0.0f;
        s_f[tid] = val;
    }
    __syncthreads();

    // ---- fold BN params (per output channel o) ----
    const float s1 = g1[o] / sqrtf(v1[o] + 1e-5f);
    const float t1 = b1[o] - m1[o] * s1;
    const float s2 = g2[o] / sqrtf(v2[o] + 1e-5f);
    const float t2 = b2[o] - m2[o] * s2;

    // ---- layer 1: 6 -> 64, BN, ReLU (points incl. padded rows) ----
    #pragma unroll
    for (int j = 0; j < 8; ++j) {
        int n = ng * 8 + j;
        const float* f = &s_f[n * 6];
        float acc = f[0] * s_w1[0 * 64 + o];
        acc = fmaf(f[1], s_w1[1 * 64 + o], acc);
        acc = fmaf(f[2], s_w1[2 * 64 + o], acc);
        acc = fmaf(f[3], s_w1[3 * 64 + o], acc);
        acc = fmaf(f[4], s_w1[4 * 64 + o], acc);
        acc = fmaf(f[5], s_w1[5 * 64 + o], acc);
        float h = fmaf(acc, s1, t1);
        s_h1[n * 64 + o] = fmaxf(h, 0.0f);
    }
    __syncthreads();

    // ---- layer 2: 64 -> 64, BN, running max over points ----
    float mv = -FLT_MAX;
    #pragma unroll
    for (int j = 0; j < 8; ++j) {
        int n = ng * 8 + j;
        const float* h = &s_h1[n * 64];
        float acc = 0.0f;
        #pragma unroll
        for (int c = 0; c < 64; ++c)
            acc = fmaf(h[c], s_w2[c * 65 + o], acc);
        float val = fmaf(acc, s2, t2);
        mv = fmaxf(mv, val);
    }
    s_part[ng * 64 + o] = mv;
    __syncthreads();

    if (tid < 64) {
        float m0 = fmaxf(fmaxf(s_part[tid], s_part[64 + tid]),
                         fmaxf(s_part[128 + tid], s_part[192 + tid]));
        g_pooled[p * 64 + tid] = m0;
    }
}

// ---------------------------------------------------------------------------
// Kernel 4: emit pseudo-image (B, C, Y, X). One block per (b, y) row.
// Fully coalesced output writes; winner row cached in smem; pooled gathers
// hit L2 (16 MB array).
// ---------------------------------------------------------------------------
__global__ __launch_bounds__(256) void emit_k(float* __restrict__ out, int B) {
    __shared__ int s_wi[XG];
    int b = blockIdx.x / YG;
    int y = blockIdx.x % YG;
    for (int x = threadIdx.x; x < XG; x += blockDim.x)
        s_wi[x] = g_winner[(b * XG + x) * YG + y];
    __syncthreads();

    const int total = CO * XG;
    for (int i = threadIdx.x; i < total; i += blockDim.x) {
        int c = i / XG;
        int x = i - c * XG;
        int wi = s_wi[x];
        float v = (wi >= 0) ? g_pooled[wi * 64 + c] : 0.0f;
        out[(((long long)b * CO + c) * YG + y) * XG + x] = v;
    }
}

// ---------------------------------------------------------------------------
// kernel_launch — graph-capturable, allocation-free
//
// Input order (setup_inputs dict): pillars, coors_batch, npoints_per_pillar,
//   [batch_size?], W1, g1, b1, m1, v1, W2, g2, b2, m2, v2
// batch_size is a Python scalar and may or may not occupy a d_in slot:
// detect via in_sizes (W1 has exactly 384 elements).
// coors/npoints: JAX default (x64 disabled) => int32 on device.
// ---------------------------------------------------------------------------
extern "C" void kernel_launch(void* const* d_in, const int* in_sizes, int n_in,
                              void* d_out, int out_size) {
    const float* pillars = (const float*)d_in[0];
    const int*   coors   = (const int*)d_in[1];
    const int*   npts    = (const int*)d_in[2];

    int wbase = (in_sizes[3] == 384) ? 3 : 4;  // skip batch_size slot if present
    const float* W1 = (const float*)d_in[wbase + 0];
    const float* g1 = (const float*)d_in[wbase + 1];
    const float* b1 = (const float*)d_in[wbase + 2];
    const float* m1 = (const float*)d_in[wbase + 3];
    const float* v1 = (const float*)d_in[wbase + 4];
    const float* W2 = (const float*)d_in[wbase + 5];
    const float* g2 = (const float*)d_in[wbase + 6];
    const float* b2 = (const float*)d_in[wbase + 7];
    const float* m2 = (const float*)d_in[wbase + 8];
    const float* v2 = (const float*)d_in[wbase + 9];

    int P = in_sizes[0] / (NPT * 4);
    int B = out_size / (CO * XG * YG);
    if (B > BMAX) B = BMAX;
    if (P > PMAX) P = PMAX;
    int win = B * XG * YG;

    init_winner_k<<<(win + 255) / 256, 256>>>(win);
    winner_k<<<(P + 255) / 256, 256>>>(coors, P, B);
    mlp_k<<<P, 256>>>(pillars, coors, npts,
                      W1, g1, b1, m1, v1, W2, g2, b2, m2, v2);
    emit_k<<<B * YG, 256>>>((float*)d_out, B);
}

// round 7
// speedup vs baseline: 2.1886x; 2.1886x over previous
#include <cuda_runtime.h>
#include <math.h>
#include <float.h>

#define XG 432
#define YG 496
#define CO 64
#define NPT 32
#define PMAX 64000
#define BMAX 4

// Scratch (no allocations allowed anywhere)
__device__ int   g_winner[BMAX * XG * YG];
__device__ float g_pooled[PMAX * CO];

typedef unsigned long long ull;

__device__ __forceinline__ ull dup2(float x) {
    ull r; asm("mov.b64 %0, {%1, %1};" : "=l"(r) : "f"(x)); return r;
}
__device__ __forceinline__ ull fma2(ull a, ull b, ull c) {
    ull d; asm("fma.rn.f32x2 %0, %1, %2, %3;" : "=l"(d) : "l"(a), "l"(b), "l"(c));
    return d;
}
__device__ __forceinline__ float2 unpack2(ull v) {
    float2 f; asm("mov.b64 {%0, %1}, %2;" : "=f"(f.x), "=f"(f.y) : "l"(v));
    return f;
}

// ---------------------------------------------------------------------------
// Kernel 1: reset winner map
// ---------------------------------------------------------------------------
__global__ void init_winner_k(int n) {
    int i = blockIdx.x * blockDim.x + threadIdx.x;
    if (i < n) g_winner[i] = -1;
}

// ---------------------------------------------------------------------------
// Kernel 2: last-pillar-index-wins per BEV cell (deterministic via atomicMax)
// ---------------------------------------------------------------------------
__global__ void winner_k(const int* __restrict__ coors, int P, int B) {
    int p = blockIdx.x * blockDim.x + threadIdx.x;
    if (p >= P) return;
    int b = coors[4 * p + 0];
    int x = coors[4 * p + 1];
    int y = coors[4 * p + 2];
    if ((unsigned)b >= (unsigned)B || (unsigned)x >= XG || (unsigned)y >= YG)
        return;
    atomicMax(&g_winner[(b * XG + x) * YG + y], p);
}

// ---------------------------------------------------------------------------
// Kernel 3: PFN, 2 pillars per block, 128 threads.
//   Layer2 = register-blocked GEMM with packed f32x2 FMA.
//   Warp tile: 32 points (one pillar) x 32 channels.
//   Lane: pg = lane&7 (4 points each), cg = lane>>3 (8 ch = 4 ch-pairs each).
// ---------------------------------------------------------------------------
#define W2STRIDE 68   // floats per k-row of s_w2t (16B-aligned, bank-spread)

__global__ __launch_bounds__(128) void mlp_k(
    const float* __restrict__ pillars,
    const int*   __restrict__ coors,
    const int*   __restrict__ npoints,
    const float* __restrict__ W1, const float* __restrict__ g1,
    const float* __restrict__ b1, const float* __restrict__ m1,
    const float* __restrict__ v1,
    const float* __restrict__ W2, const float* __restrict__ g2,
    const float* __restrict__ b2, const float* __restrict__ m2,
    const float* __restrict__ v2, int P)
{
    __shared__ float s_w2t[64 * W2STRIDE]; // [k][o] transposed W2       (17.4KB)
    __shared__ float s_h1[64 * 64];        // [k][n] layer-1 activations (16KB)
    __shared__ float s_w1t[64 * 8];        // [o][c0..c5, bias, pad] folded BN1
    __shared__ float s_f[64 * 9];          // features, stride 9 (bank-spread)
    __shared__ float s_s2[64];
    __shared__ float s_t2[64];

    const int tid  = threadIdx.x;
    const int w    = tid >> 5;
    const int lane = tid & 31;

    // ---- stage W2 transposed: read coalesced, store [k][o] ----
    #pragma unroll
    for (int i = tid; i < 4096; i += 128) {
        int o = i >> 6, k = i & 63;
        s_w2t[k * W2STRIDE + o] = W2[i];
    }
    // ---- stage folded W1 (scale s1 into weights, t1 as bias) ----
    if (tid < 64) {
        int o = tid;
        float s1 = g1[o] / sqrtf(v1[o] + 1e-5f);
        float t1 = b1[o] - m1[o] * s1;
        #pragma unroll
        for (int c = 0; c < 6; ++c) s_w1t[o * 8 + c] = W1[o * 6 + c] * s1;
        s_w1t[o * 8 + 6] = t1;
        s_w1t[o * 8 + 7] = 0.0f;
    } else {
        int o = tid - 64;
        float s2 = g2[o] / sqrtf(v2[o] + 1e-5f);
        s_s2[o] = s2;
        s_t2[o] = b2[o] - m2[o] * s2;
    }

    // ---- feature phase: warp 0 -> pillar 0, warp 1 -> pillar 1 ----
    if (w < 2) {
        int pil = blockIdx.x * 2 + w;
        if (pil < P) {
            float4 pt = *(const float4*)&pillars[(pil * 32 + lane) * 4];
            float sx = pt.x, sy = pt.y, sz = pt.z;
            #pragma unroll
            for (int off = 16; off > 0; off >>= 1) {
                sx += __shfl_xor_sync(0xffffffffu, sx, off);
                sy += __shfl_xor_sync(0xffffffffu, sy, off);
                sz += __shfl_xor_sync(0xffffffffu, sz, off);
            }
            int   npf = npoints[pil];
            float fn  = (float)npf;
            float cx = sx / fn, cy = sy / fn, cz = sz / fn;
            float px = (float)coors[4 * pil + 1] * 0.16f + 0.08f;
            float py = (float)coors[4 * pil + 2] * 0.16f - 39.6f;
            float msk = (lane < npf) ? 1.0f : 0.0f;
            int n = w * 32 + lane;
            s_f[n * 9 + 0] = pt.z * msk;
            s_f[n * 9 + 1] = (pt.x - cx) * msk;
            s_f[n * 9 + 2] = (pt.y - cy) * msk;
            s_f[n * 9 + 3] = (pt.z - cz) * msk;
            s_f[n * 9 + 4] = (pt.x - px) * msk;
            s_f[n * 9 + 5] = (pt.y - py) * msk;
        }
    }
    __syncthreads();

    // ---- layer 1: 6 -> 64 per point, ReLU, store transposed [o][n] ----
    {
        int n = tid >> 1, half = tid & 1;
        const float* fp = &s_f[n * 9];
        float f0 = fp[0], f1 = fp[1], f2 = fp[2];
        float f3 = fp[3], f4 = fp[4], f5 = fp[5];
        #pragma unroll 8
        for (int j = 0; j < 32; ++j) {
            int o = half * 32 + j;
            float4 a = *(const float4*)&s_w1t[o * 8];
            float4 b = *(const float4*)&s_w1t[o * 8 + 4];
            float acc = b.z;                 // bias t1
            acc = fmaf(f0, a.x, acc);
            acc = fmaf(f1, a.y, acc);
            acc = fmaf(f2, a.z, acc);
            acc = fmaf(f3, a.w, acc);
            acc = fmaf(f4, b.x, acc);
            acc = fmaf(f5, b.y, acc);
            s_h1[o * 64 + n] = fmaxf(acc, 0.0f);
        }
    }
    __syncthreads();

    // ---- layer 2: 64x64 GEMM over 64 points, f32x2 packed ----
    const int pg  = lane & 7;
    const int cg  = lane >> 3;
    const int ptb = (w >> 1) * 32 + pg * 4;        // 4 points
    const int chb = (w & 1) * 32 + cg * 8;         // 8 channels = 4 ch-pairs

    ull acc[4][4];
    #pragma unroll
    for (int p = 0; p < 4; ++p)
        #pragma unroll
        for (int j = 0; j < 4; ++j) acc[p][j] = 0ULL;

    #pragma unroll 4
    for (int k = 0; k < 64; ++k) {
        float4 hv = *(const float4*)&s_h1[k * 64 + ptb];
        ull h0 = dup2(hv.x), h1d = dup2(hv.y), h2 = dup2(hv.z), h3 = dup2(hv.w);
        ulonglong2 W0 = *(const ulonglong2*)&s_w2t[k * W2STRIDE + chb];
        ulonglong2 W1v = *(const ulonglong2*)&s_w2t[k * W2STRIDE + chb + 4];
        acc[0][0] = fma2(h0, W0.x, acc[0][0]);
        acc[0][1] = fma2(h0, W0.y, acc[0][1]);
        acc[0][2] = fma2(h0, W1v.x, acc[0][2]);
        acc[0][3] = fma2(h0, W1v.y, acc[0][3]);
        acc[1][0] = fma2(h1d, W0.x, acc[1][0]);
        acc[1][1] = fma2(h1d, W0.y, acc[1][1]);
        acc[1][2] = fma2(h1d, W1v.x, acc[1][2]);
        acc[1][3] = fma2(h1d, W1v.y, acc[1][3]);
        acc[2][0] = fma2(h2, W0.x, acc[2][0]);
        acc[2][1] = fma2(h2, W0.y, acc[2][1]);
        acc[2][2] = fma2(h2, W1v.x, acc[2][2]);
        acc[2][3] = fma2(h2, W1v.y, acc[2][3]);
        acc[3][0] = fma2(h3, W0.x, acc[3][0]);
        acc[3][1] = fma2(h3, W0.y, acc[3][1]);
        acc[3][2] = fma2(h3, W1v.x, acc[3][2]);
        acc[3][3] = fma2(h3, W1v.y, acc[3][3]);
    }

    // ---- epilogue: BN2, per-pillar max over points ----
    float mx[8];
    #pragma unroll
    for (int j = 0; j < 4; ++j) {
        float s2l = s_s2[chb + 2 * j],     t2l = s_t2[chb + 2 * j];
        float s2h = s_s2[chb + 2 * j + 1], t2h = s_t2[chb + 2 * j + 1];
        float ml = -FLT_MAX, mh = -FLT_MAX;
        #pragma unroll
        for (int p = 0; p < 4; ++p) {
            float2 v = unpack2(acc[p][j]);
            ml = fmaxf(ml, fmaf(v.x, s2l, t2l));
            mh = fmaxf(mh, fmaf(v.y, s2h, t2h));
        }
        mx[2 * j]     = ml;
        mx[2 * j + 1] = mh;
    }
    // reduce max over the 8 point-groups (pg = lane bits 0..2)
    #pragma unroll
    for (int off = 1; off < 8; off <<= 1) {
        #pragma unroll
        for (int i = 0; i < 8; ++i)
            mx[i] = fmaxf(mx[i], __shfl_xor_sync(0xffffffffu, mx[i], off));
    }
    if (pg == 0) {
        int pil = blockIdx.x * 2 + (w >> 1);
        if (pil < P) {
            *(float4*)&g_pooled[pil * 64 + chb] =
                make_float4(mx[0], mx[1], mx[2], mx[3]);
            *(float4*)&g_pooled[pil * 64 + chb + 4] =
                make_float4(mx[4], mx[5], mx[6], mx[7]);
        }
    }
}

// ---------------------------------------------------------------------------
// Kernel 4: emit pseudo-image (B, C, Y, X). grid = (YG, B).
// c-outer loop with additive pointer -> no integer div/mod.
// ---------------------------------------------------------------------------
__global__ __launch_bounds__(256) void emit_k(float* __restrict__ out) {
    __shared__ int s_wi[XG];
    const int y = blockIdx.x;
    const int b = blockIdx.y;
    for (int x = threadIdx.x; x < XG; x += 256)
        s_wi[x] = g_winner[(b * XG + x) * YG + y];
    __syncthreads();

    float* orow = out + ((long long)(b * CO) * YG + y) * XG;
    #pragma unroll 1
    for (int c = 0; c < CO; ++c) {
        for (int x = threadIdx.x; x < XG; x += 256) {
            int wi = s_wi[x];
            orow[x] = (wi >= 0) ? g_pooled[wi * 64 + c] : 0.0f;
        }
        orow += (long long)YG * XG;
    }
}

// ---------------------------------------------------------------------------
// kernel_launch — graph-capturable, allocation-free
// ---------------------------------------------------------------------------
extern "C" void kernel_launch(void* const* d_in, const int* in_sizes, int n_in,
                              void* d_out, int out_size) {
    const float* pillars = (const float*)d_in[0];
    const int*   coors   = (const int*)d_in[1];
    const int*   npts    = (const int*)d_in[2];

    int wbase = (in_sizes[3] == 384) ? 3 : 4;  // skip batch_size slot if present
    const float* W1 = (const float*)d_in[wbase + 0];
    const float* g1 = (const float*)d_in[wbase + 1];
    const float* b1 = (const float*)d_in[wbase + 2];
    const float* m1 = (const float*)d_in[wbase + 3];
    const float* v1 = (const float*)d_in[wbase + 4];
    const float* W2 = (const float*)d_in[wbase + 5];
    const float* g2 = (const float*)d_in[wbase + 6];
    const float* b2 = (const float*)d_in[wbase + 7];
    const float* m2 = (const float*)d_in[wbase + 8];
    const float* v2 = (const float*)d_in[wbase + 9];

    int P = in_sizes[0] / (NPT * 4);
    int B = out_size / (CO * XG * YG);
    if (B > BMAX) B = BMAX;
    if (P > PMAX) P = PMAX;
    int win = B * XG * YG;

    init_winner_k<<<(win + 255) / 256, 256>>>(win);
    winner_k<<<(P + 255) / 256, 256>>>(coors, P, B);
    mlp_k<<<(P + 1) / 2, 128>>>(pillars, coors, npts,
                                W1, g1, b1, m1, v1, W2, g2, b2, m2, v2, P);
    emit_k<<<dim3(YG, B), 256>>>((float*)d_out);
}